// round 1
// baseline (speedup 1.0000x reference)
#include <cuda_runtime.h>

// VQC_Registers_BS_density: 16 beam-splitter layers collapse analytically.
//
// State index s = 32*a + b (a,b in [0,32)).
//   Even layers (reg1): 2x2 block B(theta)=[[sin,cos],[-cos,sin]] on pairs (a=2k, 2k+1).
//   Odd layers  (reg2): same block on pairs (b=2m, 2m+1).
// B(theta) = R(theta - pi/2) with R the standard rotation. All even layers share one
// pairing, all odd layers share one pairing, and the two commute. Eight compositions:
// R(sum_even - 4*pi) = R(sum_even). So the full circuit is
//   U = R_a(Pa) (x) R_b(Pb),  Pa = sum(theta_even), Pb = sum(theta_odd)
// and rho_out = U rho U^T factors into four independent pairwise Givens mixes on the
// indices (a1, b1, a2, b2) of rho viewed as [32,32,32,32]. Each disjoint 2x2x2x2 block
// of 16 elements transforms independently -> one thread per block, single kernel,
// 8 MB total traffic.

#define MIX(a0, a1, cc, ss) do { float _t0 = (a0), _t1 = (a1); \
    (a0) = (cc) * _t0 - (ss) * _t1; \
    (a1) = (ss) * _t0 + (cc) * _t1; } while (0)

__global__ __launch_bounds__(256) void vqc_bs_density_kernel(
    const float* __restrict__ rho,
    const float* __restrict__ angles,
    float* __restrict__ out)
{
    const int tid = blockIdx.x * blockDim.x + threadIdx.x;  // 0..65535

    // Composed angles (uniform across all threads; angle loads broadcast from L1).
    float suma = 0.f, sumb = 0.f;
#pragma unroll
    for (int l = 0; l < 16; l += 2) suma += __ldg(&angles[l]);
#pragma unroll
    for (int l = 1; l < 16; l += 2) sumb += __ldg(&angles[l]);
    float ca, sa, cb, sb;
    sincosf(suma, &sa, &ca);
    sincosf(sumb, &sb, &cb);

    // Block coordinates: k = a1-pair, m = b1-pair, p = a2-pair, q = b2-pair.
    const int q = tid & 15;
    const int p = (tid >> 4) & 15;
    const int m = (tid >> 8) & 15;
    const int k = tid >> 12;

    const int r = (k << 6) + (m << 1);   // row    = 32*(2k) + 2m
    const int c = (p << 6) + (q << 1);   // column = 32*(2p) + 2q
    const float* base = rho + r * 1024 + c;
    float* obase = out + r * 1024 + c;

    // x[i1][j1][i2][j2]
    float x[2][2][2][2];
#pragma unroll
    for (int i1 = 0; i1 < 2; i1++)
#pragma unroll
        for (int j1 = 0; j1 < 2; j1++)
#pragma unroll
            for (int i2 = 0; i2 < 2; i2++) {
                const float2 v = *reinterpret_cast<const float2*>(
                    base + (i1 * 32 + j1) * 1024 + i2 * 32);
                x[i1][j1][i2][0] = v.x;
                x[i1][j1][i2][1] = v.y;
            }

    // Left multiply by U: rotate i1 with (ca,sa), then j1 with (cb,sb).
#pragma unroll
    for (int j1 = 0; j1 < 2; j1++)
#pragma unroll
        for (int i2 = 0; i2 < 2; i2++)
#pragma unroll
            for (int j2 = 0; j2 < 2; j2++)
                MIX(x[0][j1][i2][j2], x[1][j1][i2][j2], ca, sa);
#pragma unroll
    for (int i1 = 0; i1 < 2; i1++)
#pragma unroll
        for (int i2 = 0; i2 < 2; i2++)
#pragma unroll
            for (int j2 = 0; j2 < 2; j2++)
                MIX(x[i1][0][i2][j2], x[i1][1][i2][j2], cb, sb);

    // Right multiply by U^T: rotate i2 with (ca,sa), then j2 with (cb,sb).
    // (rho U^T column mix has the same coefficient pattern as the row mix.)
#pragma unroll
    for (int i1 = 0; i1 < 2; i1++)
#pragma unroll
        for (int j1 = 0; j1 < 2; j1++)
#pragma unroll
            for (int j2 = 0; j2 < 2; j2++)
                MIX(x[i1][j1][0][j2], x[i1][j1][1][j2], ca, sa);
#pragma unroll
    for (int i1 = 0; i1 < 2; i1++)
#pragma unroll
        for (int j1 = 0; j1 < 2; j1++)
#pragma unroll
            for (int i2 = 0; i2 < 2; i2++)
                MIX(x[i1][j1][i2][0], x[i1][j1][i2][1], cb, sb);

#pragma unroll
    for (int i1 = 0; i1 < 2; i1++)
#pragma unroll
        for (int j1 = 0; j1 < 2; j1++)
#pragma unroll
            for (int i2 = 0; i2 < 2; i2++) {
                float2 v;
                v.x = x[i1][j1][i2][0];
                v.y = x[i1][j1][i2][1];
                *reinterpret_cast<float2*>(
                    obase + (i1 * 32 + j1) * 1024 + i2 * 32) = v;
            }
}

extern "C" void kernel_launch(void* const* d_in, const int* in_sizes, int n_in,
                              void* d_out, int out_size)
{
    const float* rho    = (const float*)d_in[0];  // input_state [1024,1024] f32
    const float* angles = (const float*)d_in[1];  // [16] f32
    // d_in[2..4]: cos/sin/id stacks — analytically folded away, never read.
    float* out = (float*)d_out;

    // 65536 independent 16-element blocks, one per thread.
    vqc_bs_density_kernel<<<256, 256>>>(rho, angles, out);
}